// round 9
// baseline (speedup 1.0000x reference)
#include <cuda_runtime.h>

typedef unsigned long long ull;

#define N2    128
#define MREG  16384
#define START 6
#define RPB   128            // regions per block
#define TPB   256            // 128 producers + 128 consumers
#define NBLK  (MREG / RPB)   // 128
#define T     16
#define NT    (N2 / T)       // 8

// dynamic smem: sSIp[N2] + sPredP[(N2/2)*RPB] + sFp[N2*RPB]  (ull each)
#define SMEM_BYTES (N2*8 + (N2/2)*RPB*8 + N2*RPB*8)   // 193 KB

__device__ float        g_partials[NBLK];
__device__ unsigned int g_count = 0;

__device__ __forceinline__ ull pack2(float lo, float hi) {
    ull r; asm("mov.b64 %0, {%1, %2};" : "=l"(r) : "f"(lo), "f"(hi)); return r;
}
__device__ __forceinline__ void unpack2(float& lo, float& hi, ull v) {
    asm("mov.b64 {%0, %1}, %2;" : "=f"(lo), "=f"(hi) : "l"(v));
}
__device__ __forceinline__ ull fma2(ull a, ull b, ull c) {
    ull d; asm("fma.rn.f32x2 %0, %1, %2, %3;" : "=l"(d) : "l"(a), "l"(b), "l"(c));
    return d;
}

__global__ void __launch_bounds__(TPB, 1) npi_fused(
    const float* __restrict__ rt,
    const float* __restrict__ gt,
    const float* __restrict__ SI,
    const float* __restrict__ f,
    const float* __restrict__ seed,
    float* __restrict__ out)
{
    extern __shared__ ull smem_u64[];
    ull* sSIp   = smem_u64;                    // [N2] broadcast (SI[d], SI[d-1])
    ull* sPredP = smem_u64 + N2;               // [(N2/2)][RPB] pred time-pairs
    ull* sFp    = sPredP + (N2 / 2) * RPB;     // [N2][RPB] (f_eff[d], f_eff[d-1])

    const int  tid      = threadIdx.x;
    const int  rid      = tid & (RPB - 1);
    const bool producer = (tid < RPB);
    const int  m        = blockIdx.x * RPB + rid;

    float loss = 0.f;
    float siL[T];   // producer state
    float fL[T];    // consumer state

    // ---- staging ----------------------------------------------------------
    if (producer) {
        float lo = SI[rid];
        float hi = (rid >= 1) ? SI[rid - 1] : 0.0f;
        sSIp[rid] = pack2(lo, hi);
    } else {
        float prev = 0.0f;
#pragma unroll 8
        for (int k = 0; k < N2; ++k) {
            float v = (k < 2) ? 0.0f : f[k * MREG + m];   // f_eff
            sFp[k * RPB + rid] = pack2(v, prev);
            prev = v;
        }
    }
    __syncthreads();

    if (producer) {
#pragma unroll
        for (int d = 1; d < T; ++d) siL[d] = ((const float*)sSIp)[2 * d];
        // ---- tile 0: seeds + forward-substitution triangular ----
        float rtt[T];
#pragma unroll
        for (int ii = START; ii < T; ++ii) rtt[ii] = rt[ii * MREG + m];
        float pt[T], s[T];
#pragma unroll
        for (int ii = 0; ii < START; ++ii) pt[ii] = seed[ii * MREG + m];
#pragma unroll
        for (int ii = START; ii < T; ++ii) s[ii] = 0.f;
#pragma unroll
        for (int jj = 0; jj < T; ++jj) {
            if (jj >= START) pt[jj] = rtt[jj] * s[jj];
#pragma unroll
            for (int ii = (jj + 1 > START ? jj + 1 : START); ii < T; ++ii)
                s[ii] = fmaf(siL[ii - jj], pt[jj], s[ii]);
        }
#pragma unroll
        for (int p = 0; p < 8; ++p)
            sPredP[p * RPB + rid] = pack2(pt[2 * p], pt[2 * p + 1]);
    } else {
#pragma unroll
        for (int d = 2; d < T; ++d)
            fL[d] = ((const float*)sFp)[(d * RPB + rid) * 2];
    }
    __syncthreads();

    // ---- pipelined phases: producer builds tile I, consumer eats tile I-1 --
    for (int I = 1; I <= NT; ++I) {
        if (producer && I < NT) {
            const int c = I * T;
            float rtt[T];
#pragma unroll
            for (int ii = 0; ii < T; ++ii) rtt[ii] = rt[(c + ii) * MREG + m];

            ull acc2[T];
#pragma unroll
            for (int ii = 0; ii < T; ++ii) acc2[ii] = 0ull;

            ull wrev[31];            // J = I-1 -> lag base = 1
#pragma unroll
            for (int k = 1; k < 31; ++k) wrev[k] = sSIp[1 + k];

            for (int J = I - 1;; --J) {
                ull pjp[8];
#pragma unroll
                for (int p = 0; p < 8; ++p) pjp[p] = sPredP[(J * 8 + p) * RPB + rid];
#pragma unroll
                for (int p = 0; p < 8; ++p)
#pragma unroll
                    for (int ii = 0; ii < T; ++ii)
                        acc2[ii] = fma2(wrev[ii - 2 * p + 15], pjp[p], acc2[ii]);
                if (J == 0) break;
                const int nb = c - (J - 1) * T - 15;   // slide window by 16
#pragma unroll
                for (int k = 1; k < 15; ++k) wrev[k] = wrev[k + 16];
#pragma unroll
                for (int k = 15; k < 31; ++k) wrev[k] = sSIp[nb + k];
            }

            float acc[T];
#pragma unroll
            for (int ii = 0; ii < T; ++ii) {
                float lo, hi; unpack2(lo, hi, acc2[ii]);
                acc[ii] = lo + hi;
            }
            float pt[T];
#pragma unroll
            for (int jj = 0; jj < T; ++jj) {
                pt[jj] = rtt[jj] * acc[jj];
#pragma unroll
                for (int ii = jj + 1; ii < T; ++ii)
                    acc[ii] = fmaf(siL[ii - jj], pt[jj], acc[ii]);
            }
#pragma unroll
            for (int p = 0; p < 8; ++p)
                sPredP[(I * 8 + p) * RPB + rid] = pack2(pt[2 * p], pt[2 * p + 1]);
        }

        if (!producer) {
            const int IC = I - 1;               // output tile (pred tiles <= IC ready)
            const int c  = IC * T;
            float gtt[T];
#pragma unroll
            for (int ii = 0; ii < T; ++ii) gtt[ii] = gt[(c + ii) * MREG + m];

            float dth[T];
#pragma unroll
            for (int ii = 0; ii < T; ++ii) dth[ii] = 0.f;

            { // diagonal tile: d = ii-jj in [2,15]
                ull pdp[8];
#pragma unroll
                for (int p = 0; p < 8; ++p) pdp[p] = sPredP[(IC * 8 + p) * RPB + rid];
                float pd[T];
#pragma unroll
                for (int p = 0; p < 8; ++p) unpack2(pd[2 * p], pd[2 * p + 1], pdp[p]);
#pragma unroll
                for (int jj = 0; jj < T; ++jj)
#pragma unroll
                    for (int ii = 0; ii < T; ++ii)
                        if (ii - jj >= 2)
                            dth[ii] = fmaf(fL[ii - jj], pd[jj], dth[ii]);
            }

            if (IC > 0) {
                ull acc2[T];
#pragma unroll
                for (int ii = 0; ii < T; ++ii) acc2[ii] = 0ull;

                ull wrev[31];        // J = IC-1 -> lag base = 1
#pragma unroll
                for (int k = 1; k < 31; ++k) wrev[k] = sFp[(1 + k) * RPB + rid];

                for (int J = IC - 1;; --J) {
                    ull pjp[8];
#pragma unroll
                    for (int p = 0; p < 8; ++p) pjp[p] = sPredP[(J * 8 + p) * RPB + rid];
#pragma unroll
                    for (int p = 0; p < 8; ++p)
#pragma unroll
                        for (int ii = 0; ii < T; ++ii)
                            acc2[ii] = fma2(wrev[ii - 2 * p + 15], pjp[p], acc2[ii]);
                    if (J == 0) break;
                    const int nb = c - (J - 1) * T - 15;
#pragma unroll
                    for (int k = 1; k < 15; ++k) wrev[k] = wrev[k + 16];
#pragma unroll
                    for (int k = 15; k < 31; ++k) wrev[k] = sFp[(nb + k) * RPB + rid];
                }
#pragma unroll
                for (int ii = 0; ii < T; ++ii) {
                    float lo, hi; unpack2(lo, hi, acc2[ii]);
                    dth[ii] += lo + hi;
                }
            }

#pragma unroll
            for (int ii = 0; ii < T; ++ii) {
                float dp = dth[ii];
                if (c + ii < START) dp = (c + ii == 0) ? 1e-9f : 0.f;
                const float diff = dp - gtt[ii];
                loss = fmaf(diff, diff, loss);
            }
        }
        __syncthreads();
    }

    // ================= deterministic fused reduction =================
#pragma unroll
    for (int off = 16; off; off >>= 1)
        loss += __shfl_xor_sync(0xffffffffu, loss, off);

    __shared__ float warpsum[TPB / 32];
    __shared__ bool  s_last;
    if ((tid & 31) == 0) warpsum[tid >> 5] = loss;
    __syncthreads();

    if (tid == 0) {
        float s = 0.0f;
#pragma unroll
        for (int w = 0; w < TPB / 32; ++w) s += warpsum[w];
        g_partials[blockIdx.x] = s;
        __threadfence();
        unsigned prev = atomicAdd(&g_count, 1u);
        s_last = (prev == NBLK - 1u);
    }
    __syncthreads();

    if (s_last) {
        if (tid < 32) {
            float v = 0.0f;
#pragma unroll
            for (int k = 0; k < NBLK / 32; ++k)
                v += g_partials[tid + k * 32];
#pragma unroll
            for (int off = 16; off; off >>= 1)
                v += __shfl_xor_sync(0xffffffffu, v, off);
            if (tid == 0) {
                out[0] = v * (1.0f / ((float)N2 * (float)MREG));
                g_count = 0;   // reset for graph replay
            }
        }
    }
}

extern "C" void kernel_launch(void* const* d_in, const int* in_sizes, int n_in,
                              void* d_out, int out_size)
{
    const float* rt   = (const float*)d_in[0];
    const float* gt   = (const float*)d_in[1];
    const float* SI   = (const float*)d_in[2];
    const float* f    = (const float*)d_in[3];
    const float* seed = (const float*)d_in[4];

    static bool attr_set = false;
    if (!attr_set) {
        cudaFuncSetAttribute(npi_fused,
                             cudaFuncAttributeMaxDynamicSharedMemorySize,
                             SMEM_BYTES);
        attr_set = true;
    }

    npi_fused<<<NBLK, TPB, SMEM_BYTES>>>(rt, gt, SI, f, seed, (float*)d_out);
}

// round 10
// speedup vs baseline: 1.0632x; 1.0632x over previous
#include <cuda_runtime.h>

#define N2    128
#define MREG  16384
#define START 6
#define RPB   128            // regions per block
#define TPB   512            // 4 roles x 128 threads
#define NBLK  (MREG / RPB)   // 128
#define T     16
#define NT    (N2 / T)       // 8
#define PAD   132            // floats per transposed row (16B-aligned rows)

// dynamic smem (floats): sSI[PAD] + sPredT[RPB*PAD] + sFT[RPB*PAD]
#define SMEM_FLOATS (PAD + 2 * RPB * PAD)
#define SMEM_BYTES  (SMEM_FLOATS * 4)

__device__ float        g_partials[NBLK];
__device__ unsigned int g_count = 0;

__global__ void __launch_bounds__(TPB, 1) npi_fused(
    const float* __restrict__ rt,
    const float* __restrict__ gt,
    const float* __restrict__ SI,
    const float* __restrict__ f,
    const float* __restrict__ seed,
    float* __restrict__ out)
{
    extern __shared__ float sm[];
    float* sSI    = sm;                 // [PAD]
    float* sPredT = sm + PAD;           // [RPB][PAD]  pred, per-region row
    float* sFT    = sPredT + RPB * PAD; // [RPB][PAD]  f_eff, per-region row

    const int tid = threadIdx.x;
    const int g   = tid >> 7;           // role: 0=P0,1=P1,2=C0,3=C1
    const int rid = tid & (RPB - 1);
    const int m   = blockIdx.x * RPB + rid;

    float* myPred = sPredT + rid * PAD;
    float* myF    = sFT + rid * PAD;

    // ---- staging: f (all threads, coalesced), SI (role 0) ------------------
    {
        const int k0 = g * 32;
#pragma unroll 8
        for (int k = k0; k < k0 + 32; ++k)
            myF[k] = (k < 2) ? 0.0f : f[k * MREG + m];   // f_eff
    }
    if (g == 0) sSI[rid] = SI[rid];
    if (g == 1 && rid < PAD - N2) sSI[N2 + rid] = 0.0f;  // pad
    __syncthreads();

    float siL[T];          // producers
    float fL[T];           // consumers
    float loss = 0.f;
    const int ii0 = (g == 3) ? 8 : 0;   // consumer half offset

    if (g <= 1) {
#pragma unroll
        for (int d = 1; d < T; ++d) siL[d] = sSI[d];
    } else {
#pragma unroll
        for (int d = 2; d < T; ++d) fL[d] = myF[d];
    }

    // ---- tile 0: P0 computes full seed tile ---------------------------------
    if (g == 0) {
        float rtt[T];
#pragma unroll
        for (int ii = START; ii < T; ++ii) rtt[ii] = rt[ii * MREG + m];
        float pt[T], s[T];
#pragma unroll
        for (int ii = 0; ii < START; ++ii) pt[ii] = seed[ii * MREG + m];
#pragma unroll
        for (int ii = START; ii < T; ++ii) s[ii] = 0.f;
#pragma unroll
        for (int jj = 0; jj < T; ++jj) {
            if (jj >= START) pt[jj] = rtt[jj] * s[jj];
#pragma unroll
            for (int ii = (jj + 1 > START ? jj + 1 : START); ii < T; ++ii)
                s[ii] = fmaf(siL[ii - jj], pt[jj], s[ii]);
        }
#pragma unroll
        for (int q = 0; q < 4; ++q)
            *reinterpret_cast<float4*>(myPred + 4 * q) =
                make_float4(pt[4 * q], pt[4 * q + 1], pt[4 * q + 2], pt[4 * q + 3]);
    }
    __syncthreads();

    // ---- pipelined phases ---------------------------------------------------
    float accH[8];         // P1 carry across stepA->stepB
    float rttH[8];

#pragma unroll 1
    for (int I = 1; I <= NT; ++I) {
        const int c = I * T;

        // ======== step A ========
        if (g == 0 && I < NT) {            // P0: low half of pred tile I
            float rtt[8];
#pragma unroll
            for (int q = 0; q < 8; ++q) rtt[q] = rt[(c + q) * MREG + m];
            float acc[8];
#pragma unroll
            for (int q = 0; q < 8; ++q) acc[q] = 0.f;
#pragma unroll 1
            for (int J = I - 1; J >= 0; --J) {
                const float* wp = sSI + 16 * (I - J) - 16;      // 16B aligned
                float w[28];
#pragma unroll
                for (int q = 0; q < 7; ++q)
                    *reinterpret_cast<float4*>(w + 4 * q) =
                        *reinterpret_cast<const float4*>(wp + 4 * q);
                float pj[T];
#pragma unroll
                for (int q = 0; q < 4; ++q)
                    *reinterpret_cast<float4*>(pj + 4 * q) =
                        *reinterpret_cast<const float4*>(myPred + 16 * J + 4 * q);
#pragma unroll
                for (int jj = 0; jj < T; ++jj)
#pragma unroll
                    for (int iq = 0; iq < 8; ++iq)
                        acc[iq] = fmaf(w[iq - jj + 16], pj[jj], acc[iq]);
            }
            float pt[8];
#pragma unroll
            for (int jj = 0; jj < 8; ++jj) {
                pt[jj] = rtt[jj] * acc[jj];
#pragma unroll
                for (int iq = jj + 1; iq < 8; ++iq)
                    acc[iq] = fmaf(siL[iq - jj], pt[jj], acc[iq]);
            }
#pragma unroll
            for (int q = 0; q < 2; ++q)
                *reinterpret_cast<float4*>(myPred + c + 4 * q) =
                    make_float4(pt[4 * q], pt[4 * q + 1], pt[4 * q + 2], pt[4 * q + 3]);
        }

        if (g == 1 && I < NT) {            // P1: high-half history matvec
#pragma unroll
            for (int q = 0; q < 8; ++q) rttH[q] = rt[(c + 8 + q) * MREG + m];
#pragma unroll
            for (int q = 0; q < 8; ++q) accH[q] = 0.f;
#pragma unroll 1
            for (int J = I - 1; J >= 0; --J) {
                const float* wp = sSI + 16 * (I - J) - 8;       // 16B aligned
                float w[28];
#pragma unroll
                for (int q = 0; q < 7; ++q)
                    *reinterpret_cast<float4*>(w + 4 * q) =
                        *reinterpret_cast<const float4*>(wp + 4 * q);
                float pj[T];
#pragma unroll
                for (int q = 0; q < 4; ++q)
                    *reinterpret_cast<float4*>(pj + 4 * q) =
                        *reinterpret_cast<const float4*>(myPred + 16 * J + 4 * q);
#pragma unroll
                for (int jj = 0; jj < T; ++jj)
#pragma unroll
                    for (int iq = 0; iq < 8; ++iq)
                        accH[iq] = fmaf(w[iq - jj + 16], pj[jj], accH[iq]);
            }
        }

        if (g >= 2) {                      // consumers: off-diagonal for IC = I-1
            const int IC = I - 1;
            const int c2 = IC * T;
            float dacc[8];
#pragma unroll
            for (int q = 0; q < 8; ++q) dacc[q] = 0.f;
#pragma unroll 1
            for (int J = IC - 1; J >= 0; --J) {
                const float* wp = myF + 16 * (IC - J) - 16 + ii0;  // 16B aligned
                float w[28];
#pragma unroll
                for (int q = 0; q < 7; ++q)
                    *reinterpret_cast<float4*>(w + 4 * q) =
                        *reinterpret_cast<const float4*>(wp + 4 * q);
                float pj[T];
#pragma unroll
                for (int q = 0; q < 4; ++q)
                    *reinterpret_cast<float4*>(pj + 4 * q) =
                        *reinterpret_cast<const float4*>(myPred + 16 * J + 4 * q);
#pragma unroll
                for (int jj = 0; jj < T; ++jj)
#pragma unroll
                    for (int iq = 0; iq < 8; ++iq)
                        dacc[iq] = fmaf(w[iq - jj + 16], pj[jj], dacc[iq]);
            }
            // carry dacc through the barrier in accH slot
#pragma unroll
            for (int q = 0; q < 8; ++q) accH[q] = dacc[q];
        }
        __syncthreads();

        // ======== step B ========
        if (g == 1 && I < NT) {            // P1: cross terms + high triangular
            float ptL[8];
#pragma unroll
            for (int q = 0; q < 2; ++q)
                *reinterpret_cast<float4*>(ptL + 4 * q) =
                    *reinterpret_cast<const float4*>(myPred + c + 4 * q);
#pragma unroll
            for (int jj = 0; jj < 8; ++jj)
#pragma unroll
                for (int iq = 0; iq < 8; ++iq)
                    accH[iq] = fmaf(siL[iq + 8 - jj], ptL[jj], accH[iq]);
            float ptH[8];
#pragma unroll
            for (int jj = 0; jj < 8; ++jj) {
                ptH[jj] = rttH[jj] * accH[jj];
#pragma unroll
                for (int iq = jj + 1; iq < 8; ++iq)
                    accH[iq] = fmaf(siL[iq - jj], ptH[jj], accH[iq]);
            }
#pragma unroll
            for (int q = 0; q < 2; ++q)
                *reinterpret_cast<float4*>(myPred + c + 8 + 4 * q) =
                    make_float4(ptH[4 * q], ptH[4 * q + 1], ptH[4 * q + 2], ptH[4 * q + 3]);
        }

        if (g >= 2) {                      // consumers: diagonal + MSE
            const int IC = I - 1;
            const int c2 = IC * T;
            float gtt[8];
#pragma unroll
            for (int q = 0; q < 8; ++q) gtt[q] = gt[(c2 + ii0 + q) * MREG + m];

            float pd[T];
#pragma unroll
            for (int q = 0; q < 4; ++q)
                *reinterpret_cast<float4*>(pd + 4 * q) =
                    *reinterpret_cast<const float4*>(myPred + c2 + 4 * q);
            float dacc[8];
#pragma unroll
            for (int q = 0; q < 8; ++q) dacc[q] = accH[q];

            if (ii0 == 0) {
#pragma unroll
                for (int jj = 0; jj < T; ++jj)
#pragma unroll
                    for (int iq = 0; iq < 8; ++iq)
                        if (iq - jj >= 2)
                            dacc[iq] = fmaf(fL[iq - jj], pd[jj], dacc[iq]);
            } else {
#pragma unroll
                for (int jj = 0; jj < T; ++jj)
#pragma unroll
                    for (int iq = 0; iq < 8; ++iq)
                        if (8 + iq - jj >= 2 && 8 + iq - jj <= 15)
                            dacc[iq] = fmaf(fL[8 + iq - jj], pd[jj], dacc[iq]);
            }

#pragma unroll
            for (int iq = 0; iq < 8; ++iq) {
                const int i = c2 + ii0 + iq;
                float dp = dacc[iq];
                if (i < START) dp = (i == 0) ? 1e-9f : 0.f;
                const float diff = dp - gtt[iq];
                loss = fmaf(diff, diff, loss);
            }
        }
        __syncthreads();
    }

    // ================= deterministic fused reduction =================
#pragma unroll
    for (int off = 16; off; off >>= 1)
        loss += __shfl_xor_sync(0xffffffffu, loss, off);

    __shared__ float warpsum[TPB / 32];
    __shared__ bool  s_last;
    if ((tid & 31) == 0) warpsum[tid >> 5] = loss;
    __syncthreads();

    if (tid == 0) {
        float s = 0.0f;
#pragma unroll
        for (int w = 0; w < TPB / 32; ++w) s += warpsum[w];
        g_partials[blockIdx.x] = s;
        __threadfence();
        unsigned prev = atomicAdd(&g_count, 1u);
        s_last = (prev == NBLK - 1u);
    }
    __syncthreads();

    if (s_last) {
        if (tid < 32) {
            float v = 0.0f;
#pragma unroll
            for (int k = 0; k < NBLK / 32; ++k)
                v += g_partials[tid + k * 32];
#pragma unroll
            for (int off = 16; off; off >>= 1)
                v += __shfl_xor_sync(0xffffffffu, v, off);
            if (tid == 0) {
                out[0] = v * (1.0f / ((float)N2 * (float)MREG));
                g_count = 0;   // reset for graph replay
            }
        }
    }
}

extern "C" void kernel_launch(void* const* d_in, const int* in_sizes, int n_in,
                              void* d_out, int out_size)
{
    const float* rt   = (const float*)d_in[0];
    const float* gt   = (const float*)d_in[1];
    const float* SI   = (const float*)d_in[2];
    const float* f    = (const float*)d_in[3];
    const float* seed = (const float*)d_in[4];

    static bool attr_set = false;
    if (!attr_set) {
        cudaFuncSetAttribute(npi_fused,
                             cudaFuncAttributeMaxDynamicSharedMemorySize,
                             SMEM_BYTES);
        attr_set = true;
    }

    npi_fused<<<NBLK, TPB, SMEM_BYTES>>>(rt, gt, SI, f, seed, (float*)d_out);
}